// round 2
// baseline (speedup 1.0000x reference)
#include <cuda_runtime.h>

#define N_NODES   1000000
#define DIM       128
#define B_GRAPHS  2048
#define CHUNK     128
#define G_PER_BLK 16

// Scratch (no cudaMalloc allowed): pool accumulator + transposed W
__device__ float g_pool[B_GRAPHS * DIM];
__device__ float g_Wt[DIM * DIM];

// ---------------------------------------------------------------------------
// Kernel 0a: zero the pool accumulator (graph replays re-run atomics)
// ---------------------------------------------------------------------------
__global__ void zero_pool_kernel() {
    int i = blockIdx.x * blockDim.x + threadIdx.x;
    if (i < B_GRAPHS * DIM) g_pool[i] = 0.0f;
}

// ---------------------------------------------------------------------------
// Kernel 0b: transpose W (64KB) so the GEMM reads it coalesced.
// g_Wt[k*DIM + j] = W[j*DIM + k]
// ---------------------------------------------------------------------------
__global__ void transpose_W_kernel(const float* __restrict__ W) {
    int i = blockIdx.x * blockDim.x + threadIdx.x;
    if (i < DIM * DIM) {
        int j = i >> 7;
        int k = i & (DIM - 1);
        g_Wt[k * DIM + j] = W[i];
    }
}

// ---------------------------------------------------------------------------
// Kernel 1: segment sum. segment_ids is SORTED, so each block processes
// CHUNK contiguous rows, accumulating in registers and flushing with an
// atomicAdd only at segment boundaries / chunk edges (~1.3M atomics total).
// blockDim = DIM (thread t owns dim column t); loads are fully coalesced.
// ---------------------------------------------------------------------------
__global__ void seg_sum_kernel(const float* __restrict__ h,
                               const int*   __restrict__ seg) {
    int row0 = blockIdx.x * CHUNK;
    int row1 = row0 + CHUNK;
    if (row1 > N_NODES) row1 = N_NODES;
    int t = threadIdx.x;

    int sFirst = __ldg(&seg[row0]);
    int sLast  = __ldg(&seg[row1 - 1]);

    if (sFirst == sLast) {
        // Fast path (~74% of chunks): single segment, pure streaming sum.
        float acc = 0.0f;
        #pragma unroll 8
        for (int r = row0; r < row1; ++r)
            acc += __ldg(&h[r * DIM + t]);
        atomicAdd(&g_pool[sFirst * DIM + t], acc);
    } else {
        // Boundary path: per-row segment check (sorted -> few flushes).
        float acc = 0.0f;
        int cur = sFirst;
        for (int r = row0; r < row1; ++r) {
            int   s = __ldg(&seg[r]);
            float v = __ldg(&h[r * DIM + t]);
            if (s != cur) {
                atomicAdd(&g_pool[cur * DIM + t], acc);
                acc = 0.0f;
                cur = s;
            }
            acc += v;
        }
        atomicAdd(&g_pool[cur * DIM + t], acc);
    }
}

// ---------------------------------------------------------------------------
// Kernel 2: vn_out = vn_h + relu((vn_h + pool) @ W^T + b)
// blockDim = DIM (thread j computes output column j for G_PER_BLK graphs).
// x tiles live in smem (warp-broadcast reads); W^T read coalesced from L2.
// ---------------------------------------------------------------------------
__global__ void vn_update_kernel(const float* __restrict__ vn_h,
                                 const float* __restrict__ b,
                                 float*       __restrict__ vn_out) {
    __shared__ float sx[G_PER_BLK][DIM];
    int j  = threadIdx.x;
    int g0 = blockIdx.x * G_PER_BLK;

    #pragma unroll
    for (int gl = 0; gl < G_PER_BLK; ++gl) {
        int idx = (g0 + gl) * DIM + j;
        sx[gl][j] = vn_h[idx] + g_pool[idx];
    }
    __syncthreads();

    float acc[G_PER_BLK];
    #pragma unroll
    for (int gl = 0; gl < G_PER_BLK; ++gl) acc[gl] = 0.0f;

    #pragma unroll 4
    for (int k = 0; k < DIM; ++k) {
        float w = g_Wt[k * DIM + j];   // coalesced: consecutive j
        #pragma unroll
        for (int gl = 0; gl < G_PER_BLK; ++gl)
            acc[gl] = fmaf(sx[gl][k], w, acc[gl]);  // sx: smem broadcast
    }

    float bj = __ldg(&b[j]);
    #pragma unroll
    for (int gl = 0; gl < G_PER_BLK; ++gl) {
        int idx = (g0 + gl) * DIM + j;
        float v = fmaxf(acc[gl] + bj, 0.0f);
        vn_out[idx] = vn_h[idx] + v;
    }
}

// ---------------------------------------------------------------------------
// Kernel 3: h_out = h + vn_out[segment_ids]. float4 streaming.
// 32 consecutive lanes cover one row -> seg load is warp-uniform,
// vn gather is one coalesced 512B L2-resident row per warp.
// ---------------------------------------------------------------------------
__global__ void broadcast_add_kernel(const float4* __restrict__ h4,
                                     const float4* __restrict__ vn4,
                                     const int*    __restrict__ seg,
                                     float4*       __restrict__ out4) {
    unsigned idx = blockIdx.x * blockDim.x + threadIdx.x;   // < 32M
    if (idx >= (unsigned)N_NODES * (DIM / 4)) return;
    unsigned row = idx >> 5;          // DIM/4 = 32 float4 per row
    unsigned c   = idx & 31u;
    int s = __ldg(&seg[row]);
    float4 hv = __ldg(&h4[idx]);
    float4 vv = __ldg(&vn4[(unsigned)s * 32u + c]);
    out4[idx] = make_float4(hv.x + vv.x, hv.y + vv.y,
                            hv.z + vv.z, hv.w + vv.w);
}

// ---------------------------------------------------------------------------
// Launch: out = [vn_out (B*DIM floats) | h_out (N*DIM floats)]
// ---------------------------------------------------------------------------
extern "C" void kernel_launch(void* const* d_in, const int* in_sizes, int n_in,
                              void* d_out, int out_size) {
    const float* h    = (const float*)d_in[0];
    const float* vn_h = (const float*)d_in[1];
    const float* W    = (const float*)d_in[2];
    const float* b    = (const float*)d_in[3];
    const int*   seg  = (const int*)  d_in[4];

    float* out    = (float*)d_out;
    float* vn_out = out;                       // [B, DIM]
    float* h_out  = out + B_GRAPHS * DIM;      // [N, DIM] (1MB offset, 16B-aligned)

    zero_pool_kernel<<<(B_GRAPHS * DIM + 255) / 256, 256>>>();
    transpose_W_kernel<<<(DIM * DIM + 255) / 256, 256>>>(W);
    seg_sum_kernel<<<(N_NODES + CHUNK - 1) / CHUNK, DIM>>>(h, seg);
    vn_update_kernel<<<B_GRAPHS / G_PER_BLK, DIM>>>(vn_h, b, vn_out);

    unsigned total4 = (unsigned)N_NODES * (DIM / 4);
    broadcast_add_kernel<<<(total4 + 255) / 256, 256>>>(
        (const float4*)h, (const float4*)vn_out, seg, (float4*)h_out);
}

// round 3
// speedup vs baseline: 1.1046x; 1.1046x over previous
#include <cuda_runtime.h>

#define N_NODES   1000000
#define DIM       128
#define B_GRAPHS  2048

// Scratch (no cudaMalloc allowed): transposed W for coalesced GEMM reads
__device__ float g_Wt[DIM * DIM];

// ---------------------------------------------------------------------------
// Kernel 0: transpose W (64KB).  g_Wt[k*DIM + j] = W[j*DIM + k]
// ---------------------------------------------------------------------------
__global__ void transpose_W_kernel(const float* __restrict__ W) {
    int i = blockIdx.x * blockDim.x + threadIdx.x;
    if (i < DIM * DIM) {
        int j = i >> 7;
        int k = i & (DIM - 1);
        g_Wt[k * DIM + j] = W[i];
    }
}

// ---------------------------------------------------------------------------
// Fused kernel: one block per graph (seg ids are SORTED -> contiguous range).
//   1) binary-search [start, end) of graph g
//   2) pass 1: register segment-sum over rows (no atomics, no pool buffer)
//   3) smem GEMM row: vn = vn_h + relu((vn_h + pool) @ W^T + b)
//   4) pass 2 REVERSED: h_out = h + vn  (recently-read rows hit L2)
// blockDim = DIM; thread t owns column t. All row accesses coalesced.
// ---------------------------------------------------------------------------
__global__ void fused_vn_kernel(const float* __restrict__ h,
                                const float* __restrict__ vn_h,
                                const float* __restrict__ b,
                                const int*   __restrict__ seg,
                                float*       __restrict__ vn_out,
                                float*       __restrict__ h_out) {
    __shared__ float sx[DIM];
    __shared__ int   sbounds[2];

    int g = blockIdx.x;
    int t = threadIdx.x;

    // --- bounds via binary search (threads 0,1: lower_bound(g), lower_bound(g+1))
    if (t < 2) {
        int target = g + t;
        int lo = 0, hi = N_NODES;
        while (lo < hi) {
            int mid = (lo + hi) >> 1;
            if (__ldg(&seg[mid]) < target) lo = mid + 1;
            else                           hi = mid;
        }
        sbounds[t] = lo;
    }
    __syncthreads();
    int start = sbounds[0];
    int end   = sbounds[1];

    // --- pass 1: segment sum (streaming, coalesced, MLP via unroll)
    float acc = 0.0f;
    #pragma unroll 8
    for (int r = start; r < end; ++r)
        acc += __ldg(&h[r * DIM + t]);

    // --- VN update: x = vn_h + pool; y = relu(x @ W^T + b); vn = vn_h + y
    float vh = __ldg(&vn_h[g * DIM + t]);
    sx[t] = vh + acc;
    __syncthreads();

    float acc2 = 0.0f;
    #pragma unroll 8
    for (int k = 0; k < DIM; ++k)
        acc2 = fmaf(sx[k], __ldg(&g_Wt[k * DIM + t]), acc2);   // smem bcast + coalesced L2

    float vn = vh + fmaxf(acc2 + __ldg(&b[t]), 0.0f);
    vn_out[g * DIM + t] = vn;

    // --- pass 2 (reverse order for L2 reuse of pass-1 lines): h_out = h + vn
    #pragma unroll 4
    for (int r = end - 1; r >= start; --r)
        h_out[r * DIM + t] = __ldg(&h[r * DIM + t]) + vn;
}

// ---------------------------------------------------------------------------
// Launch: out = [vn_out (B*DIM floats) | h_out (N*DIM floats)]
// ---------------------------------------------------------------------------
extern "C" void kernel_launch(void* const* d_in, const int* in_sizes, int n_in,
                              void* d_out, int out_size) {
    const float* h    = (const float*)d_in[0];
    const float* vn_h = (const float*)d_in[1];
    const float* W    = (const float*)d_in[2];
    const float* b    = (const float*)d_in[3];
    const int*   seg  = (const int*)  d_in[4];

    float* out    = (float*)d_out;
    float* vn_out = out;                       // [B, DIM]
    float* h_out  = out + B_GRAPHS * DIM;      // [N, DIM]

    transpose_W_kernel<<<(DIM * DIM + 255) / 256, 256>>>(W);
    fused_vn_kernel<<<B_GRAPHS, DIM>>>(h, vn_h, b, seg, vn_out, h_out);
}